// round 3
// baseline (speedup 1.0000x reference)
#include <cuda_runtime.h>
#include <math.h>

#define HP 138
#define WP 138
#define NB 8
#define ND 200
#define NK 32
#define H0 550
#define W0 550
#define NC 3

// ---------------- scratch (device globals; no allocations allowed) ----------
__device__ float g_gx [NB * ND * WP];   // exp(-dx^2/(2 sx^2))               [b,n,w]
__device__ float g_gyc[NB * ND * HP];   // exp(-dy^2/(2 sy^2)) * conf[b,n]   [b,n,h]
__device__ float g_fc [NB * HP * WP];   // final_conf                        [b,h,w]
__device__ float g_partial[2048];       // per-block partial sums of kernel C

// ---------------- Kernel A: separable gaussian profiles ---------------------
__global__ void gauss_kernel(const float* __restrict__ loc,
                             const float* __restrict__ conf) {
    int bn = blockIdx.x;            // b*ND + n
    int t  = threadIdx.x;
    if (t >= WP) return;            // HP == WP == 138
    float cx = loc[bn * 4 + 0];
    float cy = loc[bn * 4 + 1];
    float w  = loc[bn * 4 + 2];
    float h  = loc[bn * 4 + 3];
    float sx = fmaxf(w, 1e-3f);
    float sy = fmaxf(h, 1e-3f);
    float c  = conf[bn];

    float xs = (t + 0.5f) * (1.0f / (float)WP);
    float dx = xs - cx;
    g_gx[bn * WP + t] = __expf(-dx * dx * __fdividef(0.5f, sx * sx));

    float ys = (t + 0.5f) * (1.0f / (float)HP);
    float dy = ys - cy;
    g_gyc[bn * HP + t] = __expf(-dy * dy * __fdividef(0.5f, sy * sy)) * c;
}

// ---------------- Kernel B: fused lincomb + sigmoid + moment reduction ------
// One thread = one proto pixel (h,w). Block = 16x16 pixel tile of one batch.
// mask[b] (200x32 f32 = 25.6KB) staged in SMEM, read as broadcast float4.
// gx tile (200x16 = 12.8KB) staged in SMEM. gyc read via L1 (16 distinct rows).
__global__ __launch_bounds__(256)
void assemble_kernel(const float* __restrict__ mask,
                     const float* __restrict__ proto) {
    __shared__ float mask_s[ND * NK];   // 25600 B
    __shared__ float gx_s[ND * 16];     // 12800 B

    int b   = blockIdx.z;
    int w0  = blockIdx.x * 16;
    int h0  = blockIdx.y * 16;
    int tid = threadIdx.x;

    // stage mask[b]
    {
        const float4* msrc = (const float4*)(mask + (size_t)b * ND * NK);
        float4* mdst = (float4*)mask_s;
        #pragma unroll
        for (int i = tid; i < ND * NK / 4; i += 256) mdst[i] = msrc[i];
    }
    // stage gx tile
    for (int i = tid; i < ND * 16; i += 256) {
        int n = i >> 4, ww = i & 15;
        int gw = w0 + ww;
        gx_s[i] = (gw < WP) ? g_gx[(b * ND + n) * WP + gw] : 0.0f;
    }
    __syncthreads();

    int tx = tid & 15, ty = tid >> 4;
    int h = h0 + ty, w = w0 + tx;
    bool act = (h < HP) && (w < WP);
    int hh = act ? h : 0, wwc = act ? w : 0;

    // proto row -> registers (32 floats)
    float4 p[8];
    {
        const float4* psrc = (const float4*)(proto +
            ((size_t)(b * HP + hh) * WP + wwc) * NK);
        #pragma unroll
        for (int i = 0; i < 8; i++) p[i] = psrc[i];
    }

    const float4* mp  = (const float4*)mask_s;
    const float*  gxp = gx_s + tx;
    const float*  gyp = g_gyc + (size_t)b * ND * HP + hh;

    float s1 = 0.0f, s2 = 0.0f;
    #pragma unroll 2
    for (int n = 0; n < ND; n++) {
        float d0 = 0.f, d1 = 0.f, d2 = 0.f, d3 = 0.f;
        #pragma unroll
        for (int i = 0; i < 8; i += 4) {
            float4 m0 = mp[i + 0], m1 = mp[i + 1], m2 = mp[i + 2], m3 = mp[i + 3];
            d0 = fmaf(p[i+0].x, m0.x, d0); d0 = fmaf(p[i+0].y, m0.y, d0);
            d0 = fmaf(p[i+0].z, m0.z, d0); d0 = fmaf(p[i+0].w, m0.w, d0);
            d1 = fmaf(p[i+1].x, m1.x, d1); d1 = fmaf(p[i+1].y, m1.y, d1);
            d1 = fmaf(p[i+1].z, m1.z, d1); d1 = fmaf(p[i+1].w, m1.w, d1);
            d2 = fmaf(p[i+2].x, m2.x, d2); d2 = fmaf(p[i+2].y, m2.y, d2);
            d2 = fmaf(p[i+2].z, m2.z, d2); d2 = fmaf(p[i+2].w, m2.w, d2);
            d3 = fmaf(p[i+3].x, m3.x, d3); d3 = fmaf(p[i+3].y, m3.y, d3);
            d3 = fmaf(p[i+3].z, m3.z, d3); d3 = fmaf(p[i+3].w, m3.w, d3);
        }
        float d = (d0 + d1) + (d2 + d3);
        float a = __fdividef(1.0f, 1.0f + __expf(-d));   // sigmoid
        float mc = a * gxp[n * 16] * __ldg(gyp + n * HP);
        s1 += mc;
        s2 = fmaf(mc, mc, s2);
        mp += 8;
    }

    if (act) {
        float fc = 1.0f - __fdividef(s2, s1 + 1e-6f);
        if (isnan(fc)) fc = 0.0f;
        g_fc[(size_t)(b * HP + h) * WP + w] = fc;
    }
}

// ---------------- Kernel C: bilinear 138->550, weighted variance ------------
__global__ __launch_bounds__(256)
void finalize_kernel(const float* __restrict__ orig) {
    int p = blockIdx.x * 256 + threadIdx.x;
    float val = 0.0f;
    if (p < H0 * W0) {
        int i = p / W0, j = p % W0;
        const float scale = (float)HP / (float)H0;   // half-pixel centers
        float sy = (i + 0.5f) * scale - 0.5f;
        float sx = (j + 0.5f) * scale - 0.5f;
        float fy0 = floorf(sy), fx0 = floorf(sx);
        float fy = sy - fy0,   fx = sx - fx0;
        int y0 = (int)fy0,     x0 = (int)fx0;
        int y0c = min(max(y0, 0), HP - 1);
        int y1c = min(max(y0 + 1, 0), HP - 1);
        int x0c = min(max(x0, 0), WP - 1);
        int x1c = min(max(x0 + 1, 0), WP - 1);

        float r[NB];
        float total = 0.0f;
        #pragma unroll
        for (int b = 0; b < NB; b++) {
            const float* f = g_fc + (size_t)b * HP * WP;
            float v00 = __ldg(f + y0c * WP + x0c);
            float v01 = __ldg(f + y0c * WP + x1c);
            float v10 = __ldg(f + y1c * WP + x0c);
            float v11 = __ldg(f + y1c * WP + x1c);
            float v0 = v00 + (v01 - v00) * fx;
            float v1 = v10 + (v11 - v10) * fx;
            r[b] = v0 + (v1 - v0) * fy;
            total += r[b];
        }
        float inv_t  = __fdividef(1.0f, total);          // mean div (no eps, as ref)
        float inv_te = __fdividef(1.0f, total + 1e-6f);  // var div (+eps, as ref)

        #pragma unroll
        for (int c = 0; c < NC; c++) {
            float o[NB];
            float s = 0.0f;
            #pragma unroll
            for (int b = 0; b < NB; b++) {
                o[b] = __ldg(orig + ((size_t)(b * NC + c)) * (H0 * W0) + p);
                s = fmaf(o[b], r[b], s);
            }
            float wm = s * inv_t;
            float acc = 0.0f;
            #pragma unroll
            for (int b = 0; b < NB; b++) {
                float d = o[b] - wm;
                acc = fmaf(d * d, r[b], acc);
            }
            val += acc * inv_te;
        }
        val *= (float)NB / (float)NK;   // * B / K
    }

    __shared__ float red[256];
    red[threadIdx.x] = val;
    __syncthreads();
    #pragma unroll
    for (int s = 128; s > 0; s >>= 1) {
        if (threadIdx.x < s) red[threadIdx.x] += red[threadIdx.x + s];
        __syncthreads();
    }
    if (threadIdx.x == 0) g_partial[blockIdx.x] = red[0];
}

// ---------------- Kernel D: deterministic final reduce -----------------------
__global__ void reduce_kernel(float* __restrict__ out, int nblocks) {
    __shared__ float red[1024];
    float s = 0.0f;
    for (int i = threadIdx.x; i < nblocks; i += 1024) s += g_partial[i];
    red[threadIdx.x] = s;
    __syncthreads();
    #pragma unroll
    for (int st = 512; st > 0; st >>= 1) {
        if (threadIdx.x < st) red[threadIdx.x] += red[threadIdx.x + st];
        __syncthreads();
    }
    if (threadIdx.x == 0) out[0] = red[0];
}

// ---------------- launch ------------------------------------------------------
extern "C" void kernel_launch(void* const* d_in, const int* in_sizes, int n_in,
                              void* d_out, int out_size) {
    const float* original = (const float*)d_in[0];  // [8,3,550,550]
    const float* loc      = (const float*)d_in[1];  // [8,200,4]
    const float* maskp    = (const float*)d_in[2];  // [8,200,32]
    const float* confp    = (const float*)d_in[3];  // [8,200]
    const float* proto    = (const float*)d_in[4];  // [8,138,138,32]
    float* out = (float*)d_out;

    gauss_kernel<<<NB * ND, 160>>>(loc, confp);

    dim3 gB((WP + 15) / 16, (HP + 15) / 16, NB);
    assemble_kernel<<<gB, 256>>>(maskp, proto);

    int nb = (H0 * W0 + 255) / 256;   // 1182
    finalize_kernel<<<nb, 256>>>(original);

    reduce_kernel<<<1, 1024>>>(out, nb);
}

// round 4
// speedup vs baseline: 1.1843x; 1.1843x over previous
#include <cuda_runtime.h>
#include <math.h>

#define HP 138
#define WP 138
#define NB 8
#define ND 200
#define NP (ND/2)      // 100 detection pairs
#define NK 32
#define H0 550
#define W0 550
#define NC 3

typedef unsigned long long u64;

// ---------------- packed f32x2 helpers --------------------------------------
__device__ __forceinline__ u64 pack2(float lo, float hi) {
    u64 r; asm("mov.b64 %0, {%1, %2};" : "=l"(r) : "f"(lo), "f"(hi)); return r;
}
__device__ __forceinline__ void unpack2(u64 v, float& lo, float& hi) {
    asm("mov.b64 {%0, %1}, %2;" : "=f"(lo), "=f"(hi) : "l"(v));
}
__device__ __forceinline__ u64 fma2_(u64 a, u64 b, u64 c) {
    u64 d; asm("fma.rn.f32x2 %0, %1, %2, %3;" : "=l"(d) : "l"(a), "l"(b), "l"(c)); return d;
}
__device__ __forceinline__ u64 add2_(u64 a, u64 b) {
    u64 d; asm("add.rn.f32x2 %0, %1, %2;" : "=l"(d) : "l"(a), "l"(b)); return d;
}
__device__ __forceinline__ u64 mul2_(u64 a, u64 b) {
    u64 d; asm("mul.rn.f32x2 %0, %1, %2;" : "=l"(d) : "l"(a), "l"(b)); return d;
}
__device__ __forceinline__ float ex2_(float x) {
    float y; asm("ex2.approx.ftz.f32 %0, %1;" : "=f"(y) : "f"(x)); return y;
}
__device__ __forceinline__ float rcp_(float x) {
    float y; asm("rcp.approx.ftz.f32 %0, %1;" : "=f"(y) : "f"(x)); return y;
}

// ---------------- scratch (device globals; no allocations allowed) ----------
// Pair-interleaved gaussian profiles: lane-lo = detection 2np, lane-hi = 2np+1
__device__ u64   g_gx2[NB * NP * WP];   // exp(-dx^2/(2 sx^2))             [b,np,w]
__device__ u64   g_gy2[NB * NP * HP];   // exp(-dy^2/(2 sy^2)) * conf      [b,np,h]
__device__ float g_fc [NB * HP * WP];   // final_conf                      [b,h,w]
__device__ float g_partial[2048];       // per-block partials of finalize
__device__ unsigned int g_count;        // last-block counter

// ---------------- Kernel A: separable gaussian profiles (pair-packed) -------
__global__ void gauss_kernel(const float* __restrict__ loc,
                             const float* __restrict__ conf) {
    int bn = blockIdx.x;            // b*ND + n
    int t  = threadIdx.x;
    if (bn == 0 && t == 0) g_count = 0;   // reset finalize counter each launch
    if (t >= WP) return;            // HP == WP == 138
    int b  = bn / ND;
    int n  = bn - b * ND;
    int np = n >> 1, par = n & 1;

    float cx = loc[bn * 4 + 0];
    float cy = loc[bn * 4 + 1];
    float w  = loc[bn * 4 + 2];
    float h  = loc[bn * 4 + 3];
    float sx = fmaxf(w, 1e-3f);
    float sy = fmaxf(h, 1e-3f);
    float c  = conf[bn];

    float xs = (t + 0.5f) * (1.0f / (float)WP);
    float dx = xs - cx;
    ((float*)g_gx2)[((size_t)(b * NP + np) * WP + t) * 2 + par] =
        __expf(-dx * dx * __fdividef(0.5f, sx * sx));

    float ys = (t + 0.5f) * (1.0f / (float)HP);
    float dy = ys - cy;
    ((float*)g_gy2)[((size_t)(b * NP + np) * HP + t) * 2 + par] =
        __expf(-dy * dy * __fdividef(0.5f, sy * sy)) * c;
}

// ---------------- Kernel B: fused lincomb + sigmoid + moments (f32x2) -------
// One thread = one proto pixel. Block = 16x16 tile of one batch.
// Detections processed in pairs: lane-lo = 2np, lane-hi = 2np+1.
// mask staged in SMEM pair-interleaved so each u64 holds (m[2np][k], m[2np+1][k]).
__global__ __launch_bounds__(256, 2)
void assemble_kernel(const float* __restrict__ mask,
                     const float* __restrict__ proto) {
    __shared__ float mask2[NP * NK * 2];   // 25.6 KB, [np][k][par]

    int b   = blockIdx.z;
    int w0  = blockIdx.x * 16;
    int h0  = blockIdx.y * 16;
    int tid = threadIdx.x;

    // stage mask[b] pair-interleaved
    {
        const float4* msrc = (const float4*)(mask + (size_t)b * ND * NK);
        for (int i = tid; i < ND * NK / 4; i += 256) {
            float4 v = msrc[i];
            int n  = i >> 3;            // 8 float4 per detection row
            int k0 = (i & 7) * 4;
            int np = n >> 1, par = n & 1;
            int base = (np * NK + k0) * 2 + par;
            mask2[base + 0] = v.x;
            mask2[base + 2] = v.y;
            mask2[base + 4] = v.z;
            mask2[base + 6] = v.w;
        }
    }
    __syncthreads();

    int tx = tid & 15, ty = tid >> 4;
    int h = h0 + ty, w = w0 + tx;
    bool act = (h < HP) && (w < WP);
    int hh = act ? h : 0, wwc = act ? w : 0;

    // proto row -> broadcast-packed registers (32 u64)
    u64 pp[NK];
    {
        const float4* psrc = (const float4*)(proto +
            ((size_t)(b * HP + hh) * WP + wwc) * NK);
        #pragma unroll
        for (int i = 0; i < 8; i++) {
            float4 v = psrc[i];
            pp[i * 4 + 0] = pack2(v.x, v.x);
            pp[i * 4 + 1] = pack2(v.y, v.y);
            pp[i * 4 + 2] = pack2(v.z, v.z);
            pp[i * 4 + 3] = pack2(v.w, v.w);
        }
    }

    const ulonglong2* mrow = (const ulonglong2*)mask2;        // 16 per np
    const u64* gxp = g_gx2 + (size_t)(b * NP) * WP + wwc;
    const u64* gyp = g_gy2 + (size_t)(b * NP) * HP + hh;

    const u64 NL2E2 = pack2(-1.44269504088896f, -1.44269504088896f);
    const u64 ONE2  = pack2(1.0f, 1.0f);

    u64 s1p = 0, s2p = 0;   // packed 0.0f pair
    #pragma unroll 1
    for (int np = 0; np < NP; np++) {
        u64 a0 = 0, a1 = 0;
        #pragma unroll
        for (int t = 0; t < 16; t++) {
            ulonglong2 mm = mrow[t];
            a0 = fma2_(pp[2 * t + 0], mm.x, a0);
            a1 = fma2_(pp[2 * t + 1], mm.y, a1);
        }
        u64 d2 = add2_(a0, a1);                 // packed logits (2np, 2np+1)

        // sigmoid: 1/(1 + exp2(d * -log2e))
        u64 e2 = mul2_(d2, NL2E2);
        float elo, ehi; unpack2(e2, elo, ehi);
        elo = ex2_(elo); ehi = ex2_(ehi);
        u64 t2 = add2_(pack2(elo, ehi), ONE2);
        float tlo, thi; unpack2(t2, tlo, thi);
        u64 a2 = pack2(rcp_(tlo), rcp_(thi));

        u64 mc = mul2_(mul2_(a2, __ldg(gxp)), __ldg(gyp));
        s1p = add2_(s1p, mc);
        s2p = fma2_(mc, mc, s2p);

        mrow += 16;
        gxp  += WP;
        gyp  += HP;
    }

    float s1a, s1b, s2a, s2b;
    unpack2(s1p, s1a, s1b);
    unpack2(s2p, s2a, s2b);
    float s1 = s1a + s1b, s2 = s2a + s2b;

    if (act) {
        float fc = 1.0f - __fdividef(s2, s1 + 1e-6f);
        if (isnan(fc)) fc = 0.0f;
        g_fc[(size_t)(b * HP + h) * WP + w] = fc;
    }
}

// ---------------- Kernel C: bilinear 138->550, weighted variance, reduce ----
__global__ __launch_bounds__(256)
void finalize_kernel(const float* __restrict__ orig, float* __restrict__ out,
                     int nblocks) {
    int p = blockIdx.x * 256 + threadIdx.x;
    float val = 0.0f;
    if (p < H0 * W0) {
        int i = p / W0, j = p % W0;
        const float scale = (float)HP / (float)H0;   // half-pixel centers
        float sy = (i + 0.5f) * scale - 0.5f;
        float sx = (j + 0.5f) * scale - 0.5f;
        float fy0 = floorf(sy), fx0 = floorf(sx);
        float fy = sy - fy0,   fx = sx - fx0;
        int y0 = (int)fy0,     x0 = (int)fx0;
        int y0c = min(max(y0, 0), HP - 1);
        int y1c = min(max(y0 + 1, 0), HP - 1);
        int x0c = min(max(x0, 0), WP - 1);
        int x1c = min(max(x0 + 1, 0), WP - 1);

        float r[NB];
        float total = 0.0f;
        #pragma unroll
        for (int b = 0; b < NB; b++) {
            const float* f = g_fc + (size_t)b * HP * WP;
            float v00 = __ldg(f + y0c * WP + x0c);
            float v01 = __ldg(f + y0c * WP + x1c);
            float v10 = __ldg(f + y1c * WP + x0c);
            float v11 = __ldg(f + y1c * WP + x1c);
            float v0 = v00 + (v01 - v00) * fx;
            float v1 = v10 + (v11 - v10) * fx;
            r[b] = v0 + (v1 - v0) * fy;
            total += r[b];
        }
        float inv_t  = __fdividef(1.0f, total);          // mean div (no eps, as ref)
        float inv_te = __fdividef(1.0f, total + 1e-6f);  // var div (+eps, as ref)

        #pragma unroll
        for (int c = 0; c < NC; c++) {
            float o[NB];
            float s = 0.0f;
            #pragma unroll
            for (int b = 0; b < NB; b++) {
                o[b] = __ldg(orig + ((size_t)(b * NC + c)) * (H0 * W0) + p);
                s = fmaf(o[b], r[b], s);
            }
            float wm = s * inv_t;
            float acc = 0.0f;
            #pragma unroll
            for (int b = 0; b < NB; b++) {
                float d = o[b] - wm;
                acc = fmaf(d * d, r[b], acc);
            }
            val += acc * inv_te;
        }
        val *= (float)NB / (float)NK;   // * B / K
    }

    __shared__ float red[256];
    red[threadIdx.x] = val;
    __syncthreads();
    #pragma unroll
    for (int s = 128; s > 0; s >>= 1) {
        if (threadIdx.x < s) red[threadIdx.x] += red[threadIdx.x + s];
        __syncthreads();
    }

    __shared__ bool is_last;
    if (threadIdx.x == 0) {
        g_partial[blockIdx.x] = red[0];
        __threadfence();
        unsigned int prev = atomicAdd(&g_count, 1u);
        is_last = (prev == (unsigned int)(nblocks - 1));
    }
    __syncthreads();

    if (is_last) {
        __threadfence();
        float s = 0.0f;
        for (int i = threadIdx.x; i < nblocks; i += 256) s += g_partial[i];
        red[threadIdx.x] = s;
        __syncthreads();
        #pragma unroll
        for (int st = 128; st > 0; st >>= 1) {
            if (threadIdx.x < st) red[threadIdx.x] += red[threadIdx.x + st];
            __syncthreads();
        }
        if (threadIdx.x == 0) out[0] = red[0];
    }
}

// ---------------- launch ------------------------------------------------------
extern "C" void kernel_launch(void* const* d_in, const int* in_sizes, int n_in,
                              void* d_out, int out_size) {
    const float* original = (const float*)d_in[0];  // [8,3,550,550]
    const float* loc      = (const float*)d_in[1];  // [8,200,4]
    const float* maskp    = (const float*)d_in[2];  // [8,200,32]
    const float* confp    = (const float*)d_in[3];  // [8,200]
    const float* proto    = (const float*)d_in[4];  // [8,138,138,32]
    float* out = (float*)d_out;

    gauss_kernel<<<NB * ND, 160>>>(loc, confp);

    dim3 gB((WP + 15) / 16, (HP + 15) / 16, NB);
    assemble_kernel<<<gB, 256>>>(maskp, proto);

    int nb = (H0 * W0 + 255) / 256;   // 1182
    finalize_kernel<<<nb, 256>>>(original, out, nb);
}

// round 5
// speedup vs baseline: 1.2756x; 1.0772x over previous
#include <cuda_runtime.h>
#include <math.h>

#define HP 138
#define WP 138
#define NB 8
#define ND 200
#define NP (ND/2)      // 100 detection pairs
#define NK 32
#define H0 550
#define W0 550
#define NC 3

#define NBLK_FIN 1182  // (550*550 + 255)/256

typedef unsigned long long u64;

// ---------------- packed f32x2 helpers --------------------------------------
__device__ __forceinline__ u64 pack2(float lo, float hi) {
    u64 r; asm("mov.b64 %0, {%1, %2};" : "=l"(r) : "f"(lo), "f"(hi)); return r;
}
__device__ __forceinline__ void unpack2(u64 v, float& lo, float& hi) {
    asm("mov.b64 {%0, %1}, %2;" : "=f"(lo), "=f"(hi) : "l"(v));
}
__device__ __forceinline__ u64 fma2_(u64 a, u64 b, u64 c) {
    u64 d; asm("fma.rn.f32x2 %0, %1, %2, %3;" : "=l"(d) : "l"(a), "l"(b), "l"(c)); return d;
}
__device__ __forceinline__ u64 add2_(u64 a, u64 b) {
    u64 d; asm("add.rn.f32x2 %0, %1, %2;" : "=l"(d) : "l"(a), "l"(b)); return d;
}
__device__ __forceinline__ u64 mul2_(u64 a, u64 b) {
    u64 d; asm("mul.rn.f32x2 %0, %1, %2;" : "=l"(d) : "l"(a), "l"(b)); return d;
}
__device__ __forceinline__ float ex2_(float x) {
    float y; asm("ex2.approx.ftz.f32 %0, %1;" : "=f"(y) : "f"(x)); return y;
}
__device__ __forceinline__ float rcp_(float x) {
    float y; asm("rcp.approx.ftz.f32 %0, %1;" : "=f"(y) : "f"(x)); return y;
}

// ---------------- scratch (device globals; no allocations allowed) ----------
__device__ float g_fc [NB * HP * WP];   // final_conf  [b,h,w]
__device__ float g_partial[2048];       // per-block partials of finalize
__device__ unsigned int g_count;        // wraparound last-block counter

#define SM_MASK_BYTES (NP * NK * 2 * 4)          // 25600
#define SM_GX_BYTES   (NP * 16 * 8)              // 12800
#define SM_TOTAL      (SM_MASK_BYTES + 2 * SM_GX_BYTES)   // 51200

// ---------------- Kernel B: fully fused gaussian + lincomb + moments --------
// One thread = one proto pixel. Block = 16x16 tile of one batch.
// Detections in pairs (f32x2): lane-lo = det 2np, lane-hi = det 2np+1.
// mask staged in SMEM pair-interleaved, PRE-SCALED by -log2(e) so the packed
// dot product is directly the exp2 argument of the sigmoid.
// Gaussian profiles for this tile's 16 columns / 16 rows are computed in-block
// and kept in SMEM (gy includes conf) -> no global gaussian round trip.
__global__ __launch_bounds__(256, 2)
void assemble_kernel(const float* __restrict__ mask,
                     const float* __restrict__ proto,
                     const float* __restrict__ loc,
                     const float* __restrict__ conf) {
    extern __shared__ char smem[];
    float* mask2 = (float*)smem;                       // [np][k][par]
    u64*   gx_s  = (u64*)(smem + SM_MASK_BYTES);       // [np][16 tx]
    u64*   gy_s  = (u64*)(smem + SM_MASK_BYTES + SM_GX_BYTES); // [np][16 ty]

    int b   = blockIdx.z;
    int w0  = blockIdx.x * 16;
    int h0  = blockIdx.y * 16;
    int tid = threadIdx.x;

    const float NL2E = -1.44269504088896f;

    // ---- stage mask[b], pair-interleaved, pre-scaled by -log2(e) ----
    {
        const float4* msrc = (const float4*)(mask + (size_t)b * ND * NK);
        for (int i = tid; i < ND * NK / 4; i += 256) {
            float4 v = msrc[i];
            int n  = i >> 3;            // 8 float4 per detection row
            int k0 = (i & 7) * 4;
            int np = n >> 1, par = n & 1;
            int base = (np * NK + k0) * 2 + par;
            mask2[base + 0] = v.x * NL2E;
            mask2[base + 2] = v.y * NL2E;
            mask2[base + 4] = v.z * NL2E;
            mask2[base + 6] = v.w * NL2E;
        }
    }

    // ---- compute gaussian profiles for this tile (gy includes conf) ----
    {
        const float4* loc4 = (const float4*)(loc + (size_t)b * ND * 4);
        const float*  cf   = conf + (size_t)b * ND;
        for (int i = tid; i < NP * 16; i += 256) {
            int np = i >> 4, j = i & 15;
            float4 l0 = loc4[2 * np + 0];
            float4 l1 = loc4[2 * np + 1];
            float c0 = cf[2 * np + 0], c1 = cf[2 * np + 1];

            int gw = min(w0 + j, WP - 1);
            int gh = min(h0 + j, HP - 1);
            float xs = (gw + 0.5f) * (1.0f / (float)WP);
            float ys = (gh + 0.5f) * (1.0f / (float)HP);

            float sx0 = fmaxf(l0.z, 1e-3f), sy0 = fmaxf(l0.w, 1e-3f);
            float sx1 = fmaxf(l1.z, 1e-3f), sy1 = fmaxf(l1.w, 1e-3f);
            float ix0 = __fdividef(0.5f, sx0 * sx0);
            float iy0 = __fdividef(0.5f, sy0 * sy0);
            float ix1 = __fdividef(0.5f, sx1 * sx1);
            float iy1 = __fdividef(0.5f, sy1 * sy1);

            float dx0 = xs - l0.x, dx1 = xs - l1.x;
            float dy0 = ys - l0.y, dy1 = ys - l1.y;

            gx_s[i] = pack2(__expf(-dx0 * dx0 * ix0),
                            __expf(-dx1 * dx1 * ix1));
            gy_s[i] = pack2(__expf(-dy0 * dy0 * iy0) * c0,
                            __expf(-dy1 * dy1 * iy1) * c1);
        }
    }
    __syncthreads();

    int tx = tid & 15, ty = tid >> 4;
    int h = h0 + ty, w = w0 + tx;
    bool act = (h < HP) && (w < WP);
    int hh = act ? h : 0, wwc = act ? w : 0;

    // proto row -> broadcast-packed registers (32 u64)
    u64 pp[NK];
    {
        const float4* psrc = (const float4*)(proto +
            ((size_t)(b * HP + hh) * WP + wwc) * NK);
        #pragma unroll
        for (int i = 0; i < 8; i++) {
            float4 v = psrc[i];
            pp[i * 4 + 0] = pack2(v.x, v.x);
            pp[i * 4 + 1] = pack2(v.y, v.y);
            pp[i * 4 + 2] = pack2(v.z, v.z);
            pp[i * 4 + 3] = pack2(v.w, v.w);
        }
    }

    const ulonglong2* mrow = (const ulonglong2*)mask2;   // 16 per np
    const u64 ONE2 = pack2(1.0f, 1.0f);

    u64 s1p = 0, s2p = 0;   // packed 0.0f pair
    #pragma unroll 1
    for (int np = 0; np < NP; np++) {
        u64 gx = gx_s[np * 16 + tx];    // broadcast LDS.64
        u64 gy = gy_s[np * 16 + ty];

        u64 a0 = 0, a1 = 0;
        #pragma unroll
        for (int t = 0; t < 16; t++) {
            ulonglong2 mm = mrow[t];
            a0 = fma2_(pp[2 * t + 0], mm.x, a0);
            a1 = fma2_(pp[2 * t + 1], mm.y, a1);
        }
        u64 e2 = add2_(a0, a1);            // = -logit * log2(e), packed pair

        // sigmoid = 1 / (1 + exp2(e2))
        float elo, ehi; unpack2(e2, elo, ehi);
        elo = ex2_(elo); ehi = ex2_(ehi);
        u64 t2 = add2_(pack2(elo, ehi), ONE2);
        float tlo, thi; unpack2(t2, tlo, thi);
        u64 a2 = pack2(rcp_(tlo), rcp_(thi));

        u64 mc = mul2_(mul2_(a2, gx), gy);
        s1p = add2_(s1p, mc);
        s2p = fma2_(mc, mc, s2p);

        mrow += 16;
    }

    float s1a, s1b, s2a, s2b;
    unpack2(s1p, s1a, s1b);
    unpack2(s2p, s2a, s2b);
    float s1 = s1a + s1b, s2 = s2a + s2b;

    if (act) {
        float fc = 1.0f - __fdividef(s2, s1 + 1e-6f);
        if (isnan(fc)) fc = 0.0f;
        g_fc[(size_t)(b * HP + h) * WP + w] = fc;
    }
}

// ---------------- Kernel C: bilinear 138->550, weighted variance, reduce ----
__global__ __launch_bounds__(256)
void finalize_kernel(const float* __restrict__ orig, float* __restrict__ out) {
    int p = blockIdx.x * 256 + threadIdx.x;
    float val = 0.0f;
    if (p < H0 * W0) {
        int i = p / W0, j = p % W0;
        const float scale = (float)HP / (float)H0;   // half-pixel centers
        float sy = (i + 0.5f) * scale - 0.5f;
        float sx = (j + 0.5f) * scale - 0.5f;
        float fy0 = floorf(sy), fx0 = floorf(sx);
        float fy = sy - fy0,   fx = sx - fx0;
        int y0 = (int)fy0,     x0 = (int)fx0;
        int y0c = min(max(y0, 0), HP - 1);
        int y1c = min(max(y0 + 1, 0), HP - 1);
        int x0c = min(max(x0, 0), WP - 1);
        int x1c = min(max(x0 + 1, 0), WP - 1);

        float r[NB];
        float total = 0.0f;
        #pragma unroll
        for (int b = 0; b < NB; b++) {
            const float* f = g_fc + (size_t)b * HP * WP;
            float v00 = __ldg(f + y0c * WP + x0c);
            float v01 = __ldg(f + y0c * WP + x1c);
            float v10 = __ldg(f + y1c * WP + x0c);
            float v11 = __ldg(f + y1c * WP + x1c);
            float v0 = v00 + (v01 - v00) * fx;
            float v1 = v10 + (v11 - v10) * fx;
            r[b] = v0 + (v1 - v0) * fy;
            total += r[b];
        }
        float inv_t  = __fdividef(1.0f, total);          // mean div (no eps, as ref)
        float inv_te = __fdividef(1.0f, total + 1e-6f);  // var div (+eps, as ref)

        #pragma unroll
        for (int c = 0; c < NC; c++) {
            float o[NB];
            float s = 0.0f;
            #pragma unroll
            for (int b = 0; b < NB; b++) {
                o[b] = __ldg(orig + ((size_t)(b * NC + c)) * (H0 * W0) + p);
                s = fmaf(o[b], r[b], s);
            }
            float wm = s * inv_t;
            float acc = 0.0f;
            #pragma unroll
            for (int b = 0; b < NB; b++) {
                float d = o[b] - wm;
                acc = fmaf(d * d, r[b], acc);
            }
            val += acc * inv_te;
        }
        val *= (float)NB / (float)NK;   // * B / K
    }

    __shared__ float red[256];
    red[threadIdx.x] = val;
    __syncthreads();
    #pragma unroll
    for (int s = 128; s > 0; s >>= 1) {
        if (threadIdx.x < s) red[threadIdx.x] += red[threadIdx.x + s];
        __syncthreads();
    }

    __shared__ bool is_last;
    if (threadIdx.x == 0) {
        g_partial[blockIdx.x] = red[0];
        __threadfence();
        // wraparound counter: cycles 0..NBLK_FIN-1 forever; exactly one block
        // per launch observes NBLK_FIN-1. Deterministic across graph replays,
        // no reset needed.
        unsigned int prev = atomicInc(&g_count, NBLK_FIN - 1);
        is_last = (prev == NBLK_FIN - 1);
    }
    __syncthreads();

    if (is_last) {
        __threadfence();
        float s = 0.0f;
        for (int i = threadIdx.x; i < NBLK_FIN; i += 256) s += g_partial[i];
        red[threadIdx.x] = s;
        __syncthreads();
        #pragma unroll
        for (int st = 128; st > 0; st >>= 1) {
            if (threadIdx.x < st) red[threadIdx.x] += red[threadIdx.x + st];
            __syncthreads();
        }
        if (threadIdx.x == 0) out[0] = red[0];
    }
}

// ---------------- launch ------------------------------------------------------
extern "C" void kernel_launch(void* const* d_in, const int* in_sizes, int n_in,
                              void* d_out, int out_size) {
    const float* original = (const float*)d_in[0];  // [8,3,550,550]
    const float* loc      = (const float*)d_in[1];  // [8,200,4]
    const float* maskp    = (const float*)d_in[2];  // [8,200,32]
    const float* confp    = (const float*)d_in[3];  // [8,200]
    const float* proto    = (const float*)d_in[4];  // [8,138,138,32]
    float* out = (float*)d_out;

    static bool attr_set = false;
    if (!attr_set) {
        cudaFuncSetAttribute(assemble_kernel,
                             cudaFuncAttributeMaxDynamicSharedMemorySize,
                             SM_TOTAL);
        attr_set = true;
    }

    dim3 gB((WP + 15) / 16, (HP + 15) / 16, NB);
    assemble_kernel<<<gB, 256, SM_TOTAL>>>(maskp, proto, loc, confp);

    finalize_kernel<<<NBLK_FIN, 256>>>(original, out);
}

// round 7
// speedup vs baseline: 1.3978x; 1.0957x over previous
#include <cuda_runtime.h>
#include <cuda_bf16.h>
#include <math.h>
#include <cstdint>

#define HP 138
#define WP 138
#define NB 8
#define ND 200
#define NK 32
#define H0 550
#define W0 550
#define NC 3
#define NBLK_FIN 1182

typedef unsigned long long u64;
typedef unsigned int u32;

// ---------------- packed f32x2 helpers --------------------------------------
__device__ __forceinline__ u64 pack2(float lo, float hi) {
    u64 r; asm("mov.b64 %0, {%1, %2};" : "=l"(r) : "f"(lo), "f"(hi)); return r;
}
__device__ __forceinline__ void unpack2(u64 v, float& lo, float& hi) {
    asm("mov.b64 {%0, %1}, %2;" : "=f"(lo), "=f"(hi) : "l"(v));
}
__device__ __forceinline__ u64 fma2_(u64 a, u64 b, u64 c) {
    u64 d; asm("fma.rn.f32x2 %0, %1, %2, %3;" : "=l"(d) : "l"(a), "l"(b), "l"(c)); return d;
}
__device__ __forceinline__ u64 add2_(u64 a, u64 b) {
    u64 d; asm("add.rn.f32x2 %0, %1, %2;" : "=l"(d) : "l"(a), "l"(b)); return d;
}
__device__ __forceinline__ u64 mul2_(u64 a, u64 b) {
    u64 d; asm("mul.rn.f32x2 %0, %1, %2;" : "=l"(d) : "l"(a), "l"(b)); return d;
}
__device__ __forceinline__ float ex2_(float x) {
    float y; asm("ex2.approx.ftz.f32 %0, %1;" : "=f"(y) : "f"(x)); return y;
}
__device__ __forceinline__ float rcp_(float x) {
    float y; asm("rcp.approx.ftz.f32 %0, %1;" : "=f"(y) : "f"(x)); return y;
}

// ---------------- mma / ldmatrix wrappers (plain sm_80+ PTX) ----------------
__device__ __forceinline__ u32 smem_u32(const void* p) {
    u32 a; asm("{ .reg .u64 t; cvta.to.shared.u64 t, %1; cvt.u32.u64 %0, t; }"
               : "=r"(a) : "l"(p));
    return a;
}
__device__ __forceinline__ void ldm_x4(u32* r, u32 addr) {
    asm volatile("ldmatrix.sync.aligned.m8n8.x4.shared.b16 {%0,%1,%2,%3}, [%4];"
        : "=r"(r[0]), "=r"(r[1]), "=r"(r[2]), "=r"(r[3]) : "r"(addr));
}
__device__ __forceinline__ void ldm_x2(u32* r, u32 addr) {
    asm volatile("ldmatrix.sync.aligned.m8n8.x2.shared.b16 {%0,%1}, [%2];"
        : "=r"(r[0]), "=r"(r[1]) : "r"(addr));
}
__device__ __forceinline__ void mma_bf16(float* c, const u32* a, const u32* b) {
    asm volatile(
        "mma.sync.aligned.m16n8k16.row.col.f32.bf16.bf16.f32 "
        "{%0,%1,%2,%3}, {%4,%5,%6,%7}, {%8,%9}, {%0,%1,%2,%3};"
        : "+f"(c[0]), "+f"(c[1]), "+f"(c[2]), "+f"(c[3])
        : "r"(a[0]), "r"(a[1]), "r"(a[2]), "r"(a[3]), "r"(b[0]), "r"(b[1]));
}

// ---------------- scratch (device globals; no allocations allowed) ----------
__device__ float g_fc [NB * HP * WP];    // final_conf  [b,h,w]
__device__ float g_partial[2048];
__device__ unsigned int g_count;
// prepadded bf16 mask tiles (hi/lo), prescaled by -log2(e): rows of 80B
__device__ unsigned char g_maskb[NB][2][ND * 80];

// ---------------- SMEM layout for assemble (bytes) --------------------------
#define SM_BHI 0                       // mask hi   [200][80B]
#define SM_BLO 16000                   // mask lo   [200][80B]
#define SM_PHI 32000                   // proto hi  [128][80B]
#define SM_PLO 42240                   // proto lo  [128][80B]
#define SM_GX  52480                   // gx f32    [200][21]   (pad 21 -> conflict-free)
#define SM_GY  69280                   // gy*conf   [200][9]
#define SM_TOTAL 76480

#define NL2E (-1.44269504088896f)

// ---------------- Kernel 0: mask -> padded bf16 hi/lo rows ------------------
__global__ void maskprep_kernel(const float* __restrict__ mask) {
    int b   = blockIdx.x;
    int tid = threadIdx.x;
    const float* m = mask + (size_t)b * ND * NK;
    for (int i = tid; i < ND * NK; i += 256) {
        int n = i >> 5, k = i & 31;
        float v  = m[i] * NL2E;
        __nv_bfloat16 hb = __float2bfloat16(v);
        float lof = v - __bfloat162float(hb);
        __nv_bfloat16 lb = __float2bfloat16(lof);
        *(unsigned short*)&g_maskb[b][0][n * 80 + 2 * k] = *(unsigned short*)&hb;
        *(unsigned short*)&g_maskb[b][1][n * 80 + 2 * k] = *(unsigned short*)&lb;
    }
}

// ---------------- Kernel 1: HMMA assemble + sigmoid + moments ---------------
// CTA = 128-pixel tile (8h x 16w) of one batch, 256 threads.
// Warp wid owns M rows wid*16..+15 == pixel row h0+wid, cols w0..w0+15.
// D = proto . (mask * -log2e) via 3-term bf16-split mma.sync, f32 accum.
// sigma = rcp(1 + exp2(D)); moments over 200 detections, f32x2 packed.
__global__ __launch_bounds__(256, 2)
void assemble_kernel(const float* __restrict__ proto,
                     const float* __restrict__ loc,
                     const float* __restrict__ conf) {
    extern __shared__ char smem[];
    u32 sbase = smem_u32(smem);
    int tid  = threadIdx.x;
    int wid  = tid >> 5;
    int lane = tid & 31;
    int b   = blockIdx.z;
    int w0  = blockIdx.x * 16;
    int h0  = blockIdx.y * 8;

    // ---- staging ----
    if (tid < 128) {
        // proto row r -> bf16 hi/lo, 80B-stride rows
        int r  = tid;
        int hh = min(h0 + (r >> 4), HP - 1);
        int ww = min(w0 + (r & 15), WP - 1);
        const float4* ps = (const float4*)(proto +
            ((size_t)(b * HP + hh) * WP + ww) * NK);
        #pragma unroll
        for (int c = 0; c < 4; c++) {          // 8 elems -> 16B hi + 16B lo
            float4 q0 = ps[2 * c + 0];
            float4 q1 = ps[2 * c + 1];
            float v[8] = {q0.x, q0.y, q0.z, q0.w, q1.x, q1.y, q1.z, q1.w};
            u32 hi[4], lo[4];
            #pragma unroll
            for (int j = 0; j < 4; j++) {
                float a = v[2 * j], e = v[2 * j + 1];
                __nv_bfloat16 ha = __float2bfloat16(a);
                __nv_bfloat16 he = __float2bfloat16(e);
                float ra = a - __bfloat162float(ha);
                float re = e - __bfloat162float(he);
                __nv_bfloat16 la = __float2bfloat16(ra);
                __nv_bfloat16 le = __float2bfloat16(re);
                hi[j] = (u32)*(unsigned short*)&ha | ((u32)*(unsigned short*)&he << 16);
                lo[j] = (u32)*(unsigned short*)&la | ((u32)*(unsigned short*)&le << 16);
            }
            *(uint4*)(smem + SM_PHI + r * 80 + c * 16) = make_uint4(hi[0], hi[1], hi[2], hi[3]);
            *(uint4*)(smem + SM_PLO + r * 80 + c * 16) = make_uint4(lo[0], lo[1], lo[2], lo[3]);
        }
    } else {
        // copy prepadded mask tiles (2 x 16000B) as float4
        int t = tid - 128;
        const float4* src = (const float4*)g_maskb[b][0];   // hi then lo contiguous
        for (int j = t; j < 2000; j += 128) {
            float4 v = src[j];
            *(float4*)(smem + SM_BHI + j * 16) = v;         // BLO follows BHI
        }
    }
    // gaussian profiles: gx[200][21], gy[200][9] (gy includes conf)
    {
        float* gx_s = (float*)(smem + SM_GX);
        float* gy_s = (float*)(smem + SM_GY);
        const float4* loc4 = (const float4*)(loc + (size_t)b * ND * 4);
        const float*  cf   = conf + (size_t)b * ND;
        for (int i = tid; i < ND * 24; i += 256) {
            int n = i / 24, j = i - n * 24;
            float4 l = loc4[n];
            if (j < 16) {
                int gw = min(w0 + j, WP - 1);
                float xs = (gw + 0.5f) * (1.0f / (float)WP);
                float s = fmaxf(l.z, 1e-3f);
                float iv = __fdividef(0.5f, s * s);
                float d = xs - l.x;
                gx_s[n * 21 + j] = __expf(-d * d * iv);
            } else {
                int jj = j - 16;
                int gh = min(h0 + jj, HP - 1);
                float ys = (gh + 0.5f) * (1.0f / (float)HP);
                float s = fmaxf(l.w, 1e-3f);
                float iv = __fdividef(0.5f, s * s);
                float d = ys - l.y;
                gy_s[n * 9 + jj] = __expf(-d * d * iv) * cf[n];
            }
        }
    }
    __syncthreads();

    // ---- A fragments (proto hi/lo), loaded once ----
    u32 a_row_off = (u32)((wid * 16 + (lane & 15)) * 80 + (lane & 16));
    u32 ahi[8], alo[8];
    ldm_x4(ahi + 0, sbase + SM_PHI + a_row_off);        // k0-15
    ldm_x4(ahi + 4, sbase + SM_PHI + a_row_off + 32);   // k16-31
    ldm_x4(alo + 0, sbase + SM_PLO + a_row_off);
    ldm_x4(alo + 4, sbase + SM_PLO + a_row_off + 32);

    u32 b_off = (u32)((lane & 7) * 80 + ((lane & 8) << 1));
    u32 bhi_base = sbase + SM_BHI + b_off;
    u32 blo_base = sbase + SM_BLO + b_off;

    const float* gx_s = (const float*)(smem + SM_GX);
    const float* gy_s = (const float*)(smem + SM_GY);
    int g = lane >> 2;                // w offsets g and 8+g
    int ca = (lane & 3) * 2;          // col a within n-tile

    u64 s1r0 = 0, s2r0 = 0, s1r1 = 0, s2r1 = 0;
    #pragma unroll 1
    for (int nt = 0; nt < 25; nt++) {
        u32 brow = (u32)(nt * 8 * 80);
        float c[4] = {0.f, 0.f, 0.f, 0.f};
        u32 b0[2], b1[2];
        ldm_x2(b0, bhi_base + brow);         // hi, k0-15
        ldm_x2(b1, bhi_base + brow + 32);    // hi, k16-31
        mma_bf16(c, ahi + 0, b0);
        mma_bf16(c, ahi + 4, b1);
        mma_bf16(c, alo + 0, b0);
        mma_bf16(c, alo + 4, b1);
        ldm_x2(b0, blo_base + brow);         // lo, k0-15
        ldm_x2(b1, blo_base + brow + 32);
        mma_bf16(c, ahi + 0, b0);
        mma_bf16(c, ahi + 4, b1);

        // epilogue: c0=(r0,na) c1=(r0,nb) c2=(r1,na) c3=(r1,nb); h row = wid
        int na = nt * 8 + ca, nb = na + 1;
        float gya = gy_s[na * 9 + wid];
        float gyb = gy_s[nb * 9 + wid];
        float ga0 = gx_s[na * 21 + g]     * gya;   // (r0: w=g)
        float gb0 = gx_s[nb * 21 + g]     * gyb;
        float ga1 = gx_s[na * 21 + 8 + g] * gya;   // (r1: w=8+g)
        float gb1 = gx_s[nb * 21 + 8 + g] * gyb;

        // sigma = rcp(1 + exp2(c))   (c already = -log2e * logit)
        u64 sg0 = pack2(rcp_(1.0f + ex2_(c[0])), rcp_(1.0f + ex2_(c[1])));
        u64 sg1 = pack2(rcp_(1.0f + ex2_(c[2])), rcp_(1.0f + ex2_(c[3])));
        u64 mc0 = mul2_(sg0, pack2(ga0, gb0));
        u64 mc1 = mul2_(sg1, pack2(ga1, gb1));
        s1r0 = add2_(s1r0, mc0);
        s2r0 = fma2_(mc0, mc0, s2r0);
        s1r1 = add2_(s1r1, mc1);
        s2r1 = fma2_(mc1, mc1, s2r1);
    }

    float x, y;
    unpack2(s1r0, x, y); float s10 = x + y;
    unpack2(s2r0, x, y); float s20 = x + y;
    unpack2(s1r1, x, y); float s11 = x + y;
    unpack2(s2r1, x, y); float s21 = x + y;

    #pragma unroll
    for (int m = 1; m <= 2; m <<= 1) {
        s10 += __shfl_xor_sync(0xFFFFFFFFu, s10, m);
        s20 += __shfl_xor_sync(0xFFFFFFFFu, s20, m);
        s11 += __shfl_xor_sync(0xFFFFFFFFu, s11, m);
        s21 += __shfl_xor_sync(0xFFFFFFFFu, s21, m);
    }

    if ((lane & 3) == 0) {
        int h = h0 + wid;
        if (h < HP) {
            float* dst = g_fc + (size_t)(b * HP + h) * WP;
            int wa = w0 + g;
            if (wa < WP) {
                float fc = 1.0f - __fdividef(s20, s10 + 1e-6f);
                if (isnan(fc)) fc = 0.0f;
                dst[wa] = fc;
            }
            int wb = w0 + 8 + g;
            if (wb < WP) {
                float fc = 1.0f - __fdividef(s21, s11 + 1e-6f);
                if (isnan(fc)) fc = 0.0f;
                dst[wb] = fc;
            }
        }
    }
}

// ---------------- Kernel C: bilinear 138->550, weighted variance, reduce ----
__global__ __launch_bounds__(256)
void finalize_kernel(const float* __restrict__ orig, float* __restrict__ out) {
    int p = blockIdx.x * 256 + threadIdx.x;
    float val = 0.0f;
    if (p < H0 * W0) {
        int i = p / W0, j = p % W0;
        const float scale = (float)HP / (float)H0;
        float sy = (i + 0.5f) * scale - 0.5f;
        float sx = (j + 0.5f) * scale - 0.5f;
        float fy0 = floorf(sy), fx0 = floorf(sx);
        float fy = sy - fy0,   fx = sx - fx0;
        int y0 = (int)fy0,     x0 = (int)fx0;
        int y0c = min(max(y0, 0), HP - 1);
        int y1c = min(max(y0 + 1, 0), HP - 1);
        int x0c = min(max(x0, 0), WP - 1);
        int x1c = min(max(x0 + 1, 0), WP - 1);

        float r[NB];
        float total = 0.0f;
        #pragma unroll
        for (int b = 0; b < NB; b++) {
            const float* f = g_fc + (size_t)b * HP * WP;
            float v00 = __ldg(f + y0c * WP + x0c);
            float v01 = __ldg(f + y0c * WP + x1c);
            float v10 = __ldg(f + y1c * WP + x0c);
            float v11 = __ldg(f + y1c * WP + x1c);
            float v0 = v00 + (v01 - v00) * fx;
            float v1 = v10 + (v11 - v10) * fx;
            r[b] = v0 + (v1 - v0) * fy;
            total += r[b];
        }
        float inv_t  = __fdividef(1.0f, total);
        float inv_te = __fdividef(1.0f, total + 1e-6f);

        #pragma unroll
        for (int c = 0; c < NC; c++) {
            float o[NB];
            float s = 0.0f;
            #pragma unroll
            for (int b = 0; b < NB; b++) {
                o[b] = __ldg(orig + ((size_t)(b * NC + c)) * (H0 * W0) + p);
                s = fmaf(o[b], r[b], s);
            }
            float wm = s * inv_t;
            float acc = 0.0f;
            #pragma unroll
            for (int b = 0; b < NB; b++) {
                float d = o[b] - wm;
                acc = fmaf(d * d, r[b], acc);
            }
            val += acc * inv_te;
        }
        val *= (float)NB / (float)NK;
    }

    __shared__ float red[256];
    red[threadIdx.x] = val;
    __syncthreads();
    #pragma unroll
    for (int s = 128; s > 0; s >>= 1) {
        if (threadIdx.x < s) red[threadIdx.x] += red[threadIdx.x + s];
        __syncthreads();
    }

    __shared__ bool is_last;
    if (threadIdx.x == 0) {
        g_partial[blockIdx.x] = red[0];
        __threadfence();
        unsigned int prev = atomicInc(&g_count, NBLK_FIN - 1);
        is_last = (prev == NBLK_FIN - 1);
    }
    __syncthreads();

    if (is_last) {
        __threadfence();
        float s = 0.0f;
        for (int i = threadIdx.x; i < NBLK_FIN; i += 256) s += g_partial[i];
        red[threadIdx.x] = s;
        __syncthreads();
        #pragma unroll
        for (int st = 128; st > 0; st >>= 1) {
            if (threadIdx.x < st) red[threadIdx.x] += red[threadIdx.x + st];
            __syncthreads();
        }
        if (threadIdx.x == 0) out[0] = red[0];
    }
}

// ---------------- launch ------------------------------------------------------
extern "C" void kernel_launch(void* const* d_in, const int* in_sizes, int n_in,
                              void* d_out, int out_size) {
    const float* original = (const float*)d_in[0];  // [8,3,550,550]
    const float* loc      = (const float*)d_in[1];  // [8,200,4]
    const float* maskp    = (const float*)d_in[2];  // [8,200,32]
    const float* confp    = (const float*)d_in[3];  // [8,200]
    const float* proto    = (const float*)d_in[4];  // [8,138,138,32]
    float* out = (float*)d_out;

    static bool attr_set = false;
    if (!attr_set) {
        cudaFuncSetAttribute(assemble_kernel,
                             cudaFuncAttributeMaxDynamicSharedMemorySize,
                             SM_TOTAL);
        attr_set = true;
    }

    maskprep_kernel<<<NB, 256>>>(maskp);

    dim3 gB((WP + 15) / 16, (HP + 7) / 8, NB);   // 9 x 18 x 8 = 1296
    assemble_kernel<<<gB, 256, SM_TOTAL>>>(proto, loc, confp);

    finalize_kernel<<<NBLK_FIN, 256>>>(original, out);
}

// round 8
// speedup vs baseline: 1.9985x; 1.4298x over previous
#include <cuda_runtime.h>
#include <cuda_bf16.h>
#include <math.h>
#include <cstdint>

#define HP 138
#define WP 138
#define NB 8
#define ND 200
#define NK 32
#define H0 550
#define W0 550
#define NC 3
#define NBLK_FIN 1182
#define GSTRIDE 144            // padded gaussian row (138 -> 144, 16B aligned)

typedef unsigned long long u64;
typedef unsigned int u32;

// ---------------- packed f32x2 helpers --------------------------------------
__device__ __forceinline__ u64 pack2(float lo, float hi) {
    u64 r; asm("mov.b64 %0, {%1, %2};" : "=l"(r) : "f"(lo), "f"(hi)); return r;
}
__device__ __forceinline__ void unpack2(u64 v, float& lo, float& hi) {
    asm("mov.b64 {%0, %1}, %2;" : "=f"(lo), "=f"(hi) : "l"(v));
}
__device__ __forceinline__ u64 fma2_(u64 a, u64 b, u64 c) {
    u64 d; asm("fma.rn.f32x2 %0, %1, %2, %3;" : "=l"(d) : "l"(a), "l"(b), "l"(c)); return d;
}
__device__ __forceinline__ u64 add2_(u64 a, u64 b) {
    u64 d; asm("add.rn.f32x2 %0, %1, %2;" : "=l"(d) : "l"(a), "l"(b)); return d;
}
__device__ __forceinline__ u64 mul2_(u64 a, u64 b) {
    u64 d; asm("mul.rn.f32x2 %0, %1, %2;" : "=l"(d) : "l"(a), "l"(b)); return d;
}
__device__ __forceinline__ float tanh_(float x) {
    float y; asm("tanh.approx.f32 %0, %1;" : "=f"(y) : "f"(x)); return y;
}

// ---------------- mma / ldmatrix wrappers (plain sm_80+ PTX) ----------------
__device__ __forceinline__ u32 smem_u32(const void* p) {
    u32 a; asm("{ .reg .u64 t; cvta.to.shared.u64 t, %1; cvt.u32.u64 %0, t; }"
               : "=r"(a) : "l"(p));
    return a;
}
__device__ __forceinline__ void ldm_x4(u32* r, u32 addr) {
    asm volatile("ldmatrix.sync.aligned.m8n8.x4.shared.b16 {%0,%1,%2,%3}, [%4];"
        : "=r"(r[0]), "=r"(r[1]), "=r"(r[2]), "=r"(r[3]) : "r"(addr));
}
__device__ __forceinline__ void ldm_x2(u32* r, u32 addr) {
    asm volatile("ldmatrix.sync.aligned.m8n8.x2.shared.b16 {%0,%1}, [%2];"
        : "=r"(r[0]), "=r"(r[1]) : "r"(addr));
}
__device__ __forceinline__ void mma_bf16(float* c, const u32* a, const u32* b) {
    asm volatile(
        "mma.sync.aligned.m16n8k16.row.col.f32.bf16.bf16.f32 "
        "{%0,%1,%2,%3}, {%4,%5,%6,%7}, {%8,%9}, {%0,%1,%2,%3};"
        : "+f"(c[0]), "+f"(c[1]), "+f"(c[2]), "+f"(c[3])
        : "r"(a[0]), "r"(a[1]), "r"(a[2]), "r"(a[3]), "r"(b[0]), "r"(b[1]));
}

// ---------------- scratch (device globals; no allocations allowed) ----------
__device__ float g_fc [NB * HP * WP];     // final_conf  [b,h,w]
__device__ float g_partial[2048];
__device__ unsigned int g_count;
__device__ unsigned char g_maskb[NB][2][ND * 80];  // bf16 hi/lo, 0.5-prescaled
__device__ float g_gxT[NB * ND * GSTRIDE];         // gx            [b,n,w]
__device__ float g_gyT[NB * ND * GSTRIDE];         // gy * conf     [b,n,h]

// ---------------- SMEM layout for assemble (bytes) --------------------------
#define SM_BHI 0                       // mask hi   [200][80B]
#define SM_BLO 16000                   // mask lo   [200][80B]
#define SM_PHI 32000                   // proto hi  [128][80B]
#define SM_PLO 42240                   // proto lo  [128][80B]
#define SM_GX  52480                   // gx f32    [200][20]  (stride 20: conflict-free)
#define SM_GY  68480                   // gy*conf   [200][12]  (stride 12)
#define SM_TOTAL 78080

// ---------------- Kernel 0: prep — mask bf16 split + gaussian tables --------
// grid = NB*25 blocks; block handles 8 detections of one batch.
__global__ __launch_bounds__(256)
void prep_kernel(const float* __restrict__ mask,
                 const float* __restrict__ loc,
                 const float* __restrict__ conf) {
    int blk = blockIdx.x;
    int b   = blk / 25;
    int n0  = (blk % 25) * 8;
    int tid = threadIdx.x;

    // mask: 8 det x 32 k, one element per thread; prescale by 0.5 (tanh sigmoid)
    {
        int n = n0 + (tid >> 5), k = tid & 31;
        float v = 0.5f * mask[((size_t)b * ND + n) * NK + k];
        __nv_bfloat16 hb = __float2bfloat16(v);
        float lof = v - __bfloat162float(hb);
        __nv_bfloat16 lb = __float2bfloat16(lof);
        *(unsigned short*)&g_maskb[b][0][n * 80 + 2 * k] = *(unsigned short*)&hb;
        *(unsigned short*)&g_maskb[b][1][n * 80 + 2 * k] = *(unsigned short*)&lb;
    }

    // gaussians: 8 det x GSTRIDE x {gx, gy}; pad cols >= 138 with 0
    const float4* loc4 = (const float4*)loc;
    for (int i = tid; i < 8 * GSTRIDE * 2; i += 256) {
        int which = i / (8 * GSTRIDE);
        int r  = i - which * 8 * GSTRIDE;
        int nl = r / GSTRIDE, t = r - nl * GSTRIDE;
        int n  = n0 + nl;
        float4 l = loc4[b * ND + n];
        float out = 0.0f;
        if (which == 0) {
            if (t < WP) {
                float xs = (t + 0.5f) * (1.0f / (float)WP);
                float s  = fmaxf(l.z, 1e-3f);
                float iv = __fdividef(0.5f, s * s);
                float d  = xs - l.x;
                out = __expf(-d * d * iv);
            }
            g_gxT[((size_t)b * ND + n) * GSTRIDE + t] = out;
        } else {
            if (t < HP) {
                float ys = (t + 0.5f) * (1.0f / (float)HP);
                float s  = fmaxf(l.w, 1e-3f);
                float iv = __fdividef(0.5f, s * s);
                float d  = ys - l.y;
                out = __expf(-d * d * iv) * conf[b * ND + n];
            }
            g_gyT[((size_t)b * ND + n) * GSTRIDE + t] = out;
        }
    }
}

// ---------------- Kernel 1: HMMA assemble + tanh sigmoid + moments ----------
// CTA = 128-pixel tile (8h x 16w) of one batch, 256 threads (8 warps).
// Warp wid owns M rows wid*16..+15 == pixel row h0+wid, cols w0..w0+15.
// c = 0.5 * proto . mask via 3-term bf16-split mma.sync (3 indep accumulators,
// double-buffered B ldmatrix); sigma = 0.5 + 0.5*tanh(c).
__global__ __launch_bounds__(256, 2)
void assemble_kernel(const float* __restrict__ proto) {
    extern __shared__ char smem[];
    u32 sbase = smem_u32(smem);
    int tid  = threadIdx.x;
    int wid  = tid >> 5;
    int lane = tid & 31;
    int b   = blockIdx.z;
    int w0  = blockIdx.x * 16;
    int h0  = blockIdx.y * 8;

    // ---- staging ----
    if (tid < 128) {
        // proto row r -> bf16 hi/lo, 80B-stride rows
        int r  = tid;
        int hh = min(h0 + (r >> 4), HP - 1);
        int ww = min(w0 + (r & 15), WP - 1);
        const float4* ps = (const float4*)(proto +
            ((size_t)(b * HP + hh) * WP + ww) * NK);
        #pragma unroll
        for (int c = 0; c < 4; c++) {
            float4 q0 = ps[2 * c + 0];
            float4 q1 = ps[2 * c + 1];
            float v[8] = {q0.x, q0.y, q0.z, q0.w, q1.x, q1.y, q1.z, q1.w};
            u32 hi[4], lo[4];
            #pragma unroll
            for (int j = 0; j < 4; j++) {
                float a = v[2 * j], e = v[2 * j + 1];
                __nv_bfloat16 ha = __float2bfloat16(a);
                __nv_bfloat16 he = __float2bfloat16(e);
                float ra = a - __bfloat162float(ha);
                float re = e - __bfloat162float(he);
                __nv_bfloat16 la = __float2bfloat16(ra);
                __nv_bfloat16 le = __float2bfloat16(re);
                hi[j] = (u32)*(unsigned short*)&ha | ((u32)*(unsigned short*)&he << 16);
                lo[j] = (u32)*(unsigned short*)&la | ((u32)*(unsigned short*)&le << 16);
            }
            *(uint4*)(smem + SM_PHI + r * 80 + c * 16) = make_uint4(hi[0], hi[1], hi[2], hi[3]);
            *(uint4*)(smem + SM_PLO + r * 80 + c * 16) = make_uint4(lo[0], lo[1], lo[2], lo[3]);
        }
    } else {
        // copy prepadded mask tiles (hi+lo contiguous, 2x16000B) as float4
        int t = tid - 128;
        const float4* src = (const float4*)g_maskb[b][0];
        for (int j = t; j < 2000; j += 128)
            *(float4*)(smem + SM_BHI + j * 16) = src[j];
    }
    // gaussian tiles from precomputed tables (coalesced float4)
    {
        const float* gxg = g_gxT + (size_t)b * ND * GSTRIDE + w0;
        const float* gyg = g_gyT + (size_t)b * ND * GSTRIDE + h0;
        // gx: 200 n x 4 float4 -> [n][20] stride
        for (int i = tid; i < ND * 4; i += 256) {
            int n = i >> 2, j = i & 3;
            float4 v = *(const float4*)(gxg + n * GSTRIDE + 4 * j);
            *(float4*)(smem + SM_GX + (n * 20 + 4 * j) * 4) = v;
        }
        // gy: 200 n x 2 float4 -> [n][12] stride
        for (int i = tid; i < ND * 2; i += 256) {
            int n = i >> 1, j = i & 1;
            float4 v = *(const float4*)(gyg + n * GSTRIDE + 4 * j);
            *(float4*)(smem + SM_GY + (n * 12 + 4 * j) * 4) = v;
        }
    }
    __syncthreads();

    // ---- A fragments (proto hi/lo), loaded once ----
    u32 a_row_off = (u32)((wid * 16 + (lane & 15)) * 80 + (lane & 16));
    u32 ahi[8], alo[8];
    ldm_x4(ahi + 0, sbase + SM_PHI + a_row_off);
    ldm_x4(ahi + 4, sbase + SM_PHI + a_row_off + 32);
    ldm_x4(alo + 0, sbase + SM_PLO + a_row_off);
    ldm_x4(alo + 4, sbase + SM_PLO + a_row_off + 32);

    u32 b_off = (u32)((lane & 7) * 80 + ((lane & 8) << 1));
    u32 bhi_base = sbase + SM_BHI + b_off;
    u32 blo_base = sbase + SM_BLO + b_off;

    const float* gx_s = (const float*)(smem + SM_GX);
    const float* gy_s = (const float*)(smem + SM_GY);
    int g  = lane >> 2;
    int ca = (lane & 3) * 2;
    const u64 HALF2 = pack2(0.5f, 0.5f);

    u64 s1r0 = 0, s2r0 = 0, s1r1 = 0, s2r1 = 0;

    // double-buffered B fragments: [par][hi_k0(2), hi_k1(2), lo_k0(2), lo_k1(2)]
    u32 bb[2][8];
    ldm_x2(bb[0] + 0, bhi_base + 0);
    ldm_x2(bb[0] + 2, bhi_base + 32);
    ldm_x2(bb[0] + 4, blo_base + 0);
    ldm_x2(bb[0] + 6, blo_base + 32);

    #pragma unroll 2
    for (int nt = 0; nt < 25; nt++) {
        const u32* bc = bb[nt & 1];
        u32*       bn = bb[(nt & 1) ^ 1];
        if (nt < 24) {
            u32 brow = (u32)((nt + 1) * 8 * 80);
            ldm_x2(bn + 0, bhi_base + brow);
            ldm_x2(bn + 2, bhi_base + brow + 32);
            ldm_x2(bn + 4, blo_base + brow);
            ldm_x2(bn + 6, blo_base + brow + 32);
        }

        // 3 independent depth-2 accumulator chains
        float cm[4] = {0.f, 0.f, 0.f, 0.f};
        float cc[4] = {0.f, 0.f, 0.f, 0.f};
        float cd[4] = {0.f, 0.f, 0.f, 0.f};
        mma_bf16(cm, ahi + 0, bc + 0);   // Ahi . Bhi (k0)
        mma_bf16(cc, alo + 0, bc + 0);   // Alo . Bhi (k0)
        mma_bf16(cd, ahi + 0, bc + 4);   // Ahi . Blo (k0)
        mma_bf16(cm, ahi + 4, bc + 2);   // (k1)
        mma_bf16(cc, alo + 4, bc + 2);
        mma_bf16(cd, ahi + 4, bc + 6);

        float c0 = (cm[0] + cc[0]) + cd[0];
        float c1 = (cm[1] + cc[1]) + cd[1];
        float c2 = (cm[2] + cc[2]) + cd[2];
        float c3 = (cm[3] + cc[3]) + cd[3];

        // epilogue: c0=(r0,na) c1=(r0,nb) c2=(r1,na) c3=(r1,nb); h row = wid
        int na = nt * 8 + ca, nb = na + 1;
        float gya = gy_s[na * 12 + wid];
        float gyb = gy_s[nb * 12 + wid];
        float ga0 = gx_s[na * 20 + g]     * gya;
        float gb0 = gx_s[nb * 20 + g]     * gyb;
        float ga1 = gx_s[na * 20 + 8 + g] * gya;
        float gb1 = gx_s[nb * 20 + 8 + g] * gyb;

        // sigma = 0.5 + 0.5*tanh(c)   (mask prescaled by 0.5)
        u64 t0 = pack2(tanh_(c0), tanh_(c1));
        u64 t1 = pack2(tanh_(c2), tanh_(c3));
        u64 sg0 = fma2_(t0, HALF2, HALF2);
        u64 sg1 = fma2_(t1, HALF2, HALF2);
        u64 mc0 = mul2_(sg0, pack2(ga0, gb0));
        u64 mc1 = mul2_(sg1, pack2(ga1, gb1));
        s1r0 = add2_(s1r0, mc0);
        s2r0 = fma2_(mc0, mc0, s2r0);
        s1r1 = add2_(s1r1, mc1);
        s2r1 = fma2_(mc1, mc1, s2r1);
    }

    float x, y;
    unpack2(s1r0, x, y); float s10 = x + y;
    unpack2(s2r0, x, y); float s20 = x + y;
    unpack2(s1r1, x, y); float s11 = x + y;
    unpack2(s2r1, x, y); float s21 = x + y;

    #pragma unroll
    for (int m = 1; m <= 2; m <<= 1) {
        s10 += __shfl_xor_sync(0xFFFFFFFFu, s10, m);
        s20 += __shfl_xor_sync(0xFFFFFFFFu, s20, m);
        s11 += __shfl_xor_sync(0xFFFFFFFFu, s11, m);
        s21 += __shfl_xor_sync(0xFFFFFFFFu, s21, m);
    }

    if ((lane & 3) == 0) {
        int h = h0 + wid;
        if (h < HP) {
            float* dst = g_fc + (size_t)(b * HP + h) * WP;
            int wa = w0 + g;
            if (wa < WP) {
                float fc = 1.0f - __fdividef(s20, s10 + 1e-6f);
                if (isnan(fc)) fc = 0.0f;
                dst[wa] = fc;
            }
            int wb = w0 + 8 + g;
            if (wb < WP) {
                float fc = 1.0f - __fdividef(s21, s11 + 1e-6f);
                if (isnan(fc)) fc = 0.0f;
                dst[wb] = fc;
            }
        }
    }
}

// ---------------- Kernel C: bilinear 138->550, weighted variance, reduce ----
__global__ __launch_bounds__(256)
void finalize_kernel(const float* __restrict__ orig, float* __restrict__ out) {
    int p = blockIdx.x * 256 + threadIdx.x;
    float val = 0.0f;
    if (p < H0 * W0) {
        // hoist ALL 24 original loads first (MLP=24, hides DRAM latency)
        float o[NC * NB];
        #pragma unroll
        for (int c = 0; c < NC; c++)
            #pragma unroll
            for (int b = 0; b < NB; b++)
                o[c * NB + b] = __ldg(orig + ((size_t)(b * NC + c)) * (H0 * W0) + p);

        int i = p / W0, j = p % W0;
        const float scale = (float)HP / (float)H0;
        float sy = (i + 0.5f) * scale - 0.5f;
        float sx = (j + 0.5f) * scale - 0.5f;
        float fy0 = floorf(sy), fx0 = floorf(sx);
        float fy = sy - fy0,   fx = sx - fx0;
        int y0 = (int)fy0,     x0 = (int)fx0;
        int y0c = min(max(y0, 0), HP - 1);
        int y1c = min(max(y0 + 1, 0), HP - 1);
        int x0c = min(max(x0, 0), WP - 1);
        int x1c = min(max(x0 + 1, 0), WP - 1);

        float r[NB];
        float total = 0.0f;
        #pragma unroll
        for (int b = 0; b < NB; b++) {
            const float* f = g_fc + (size_t)b * HP * WP;
            float v00 = __ldg(f + y0c * WP + x0c);
            float v01 = __ldg(f + y0c * WP + x1c);
            float v10 = __ldg(f + y1c * WP + x0c);
            float v11 = __ldg(f + y1c * WP + x1c);
            float v0 = v00 + (v01 - v00) * fx;
            float v1 = v10 + (v11 - v10) * fx;
            r[b] = v0 + (v1 - v0) * fy;
            total += r[b];
        }
        float inv_t  = __fdividef(1.0f, total);
        float inv_te = __fdividef(1.0f, total + 1e-6f);

        #pragma unroll
        for (int c = 0; c < NC; c++) {
            float s = 0.0f;
            #pragma unroll
            for (int b = 0; b < NB; b++) s = fmaf(o[c * NB + b], r[b], s);
            float wm = s * inv_t;
            float acc = 0.0f;
            #pragma unroll
            for (int b = 0; b < NB; b++) {
                float d = o[c * NB + b] - wm;
                acc = fmaf(d * d, r[b], acc);
            }
            val += acc * inv_te;
        }
        val *= (float)NB / (float)NK;
    }

    __shared__ float red[256];
    red[threadIdx.x] = val;
    __syncthreads();
    #pragma unroll
    for (int s = 128; s > 0; s >>= 1) {
        if (threadIdx.x < s) red[threadIdx.x] += red[threadIdx.x + s];
        __syncthreads();
    }

    __shared__ bool is_last;
    if (threadIdx.x == 0) {
        g_partial[blockIdx.x] = red[0];
        __threadfence();
        unsigned int prev = atomicInc(&g_count, NBLK_FIN - 1);
        is_last = (prev == NBLK_FIN - 1);
    }
    __syncthreads();

    if (is_last) {
        __threadfence();
        float s = 0.0f;
        for (int i = threadIdx.x; i < NBLK_FIN; i += 256) s += g_partial[i];
        red[threadIdx.x] = s;
        __syncthreads();
        #pragma unroll
        for (int st = 128; st > 0; st >>= 1) {
            if (threadIdx.x < st) red[threadIdx.x] += red[threadIdx.x + st];
            __syncthreads();
        }
        if (threadIdx.x == 0) out[0] = red[0];
    }
}

// ---------------- launch ------------------------------------------------------
extern "C" void kernel_launch(void* const* d_in, const int* in_sizes, int n_in,
                              void* d_out, int out_size) {
    const float* original = (const float*)d_in[0];  // [8,3,550,550]
    const float* loc      = (const float*)d_in[1];  // [8,200,4]
    const float* maskp    = (const float*)d_in[2];  // [8,200,32]
    const float* confp    = (const float*)d_in[3];  // [8,200]
    const float* proto    = (const float*)d_in[4];  // [8,138,138,32]
    float* out = (float*)d_out;

    static bool attr_set = false;
    if (!attr_set) {
        cudaFuncSetAttribute(assemble_kernel,
                             cudaFuncAttributeMaxDynamicSharedMemorySize,
                             SM_TOTAL);
        attr_set = true;
    }

    prep_kernel<<<NB * 25, 256>>>(maskp, loc, confp);

    dim3 gB((WP + 15) / 16, (HP + 7) / 8, NB);   // 9 x 18 x 8 = 1296
    assemble_kernel<<<gB, 256, SM_TOTAL>>>(proto);

    finalize_kernel<<<NBLK_FIN, 256>>>(original, out);
}

// round 9
// speedup vs baseline: 3.2161x; 1.6093x over previous
#include <cuda_runtime.h>
#include <cuda_fp16.h>
#include <math.h>
#include <cstdint>

#define HP 138
#define WP 138
#define NB 8
#define ND 200
#define NK 32
#define H0 550
#define W0 550
#define NC 3
#define NBLK_FIN 296           // 75625 quad-pixels / 256, rounded up
#define NQUAD 75625            // 550*550/4
#define GSTRIDE 144            // padded gaussian row

typedef unsigned long long u64;
typedef unsigned int u32;

// ---------------- packed f32x2 helpers --------------------------------------
__device__ __forceinline__ u64 pack2(float lo, float hi) {
    u64 r; asm("mov.b64 %0, {%1, %2};" : "=l"(r) : "f"(lo), "f"(hi)); return r;
}
__device__ __forceinline__ void unpack2(u64 v, float& lo, float& hi) {
    asm("mov.b64 {%0, %1}, %2;" : "=f"(lo), "=f"(hi) : "l"(v));
}
__device__ __forceinline__ u64 fma2_(u64 a, u64 b, u64 c) {
    u64 d; asm("fma.rn.f32x2 %0, %1, %2, %3;" : "=l"(d) : "l"(a), "l"(b), "l"(c)); return d;
}
__device__ __forceinline__ u64 add2_(u64 a, u64 b) {
    u64 d; asm("add.rn.f32x2 %0, %1, %2;" : "=l"(d) : "l"(a), "l"(b)); return d;
}
__device__ __forceinline__ u64 mul2_(u64 a, u64 b) {
    u64 d; asm("mul.rn.f32x2 %0, %1, %2;" : "=l"(d) : "l"(a), "l"(b)); return d;
}
__device__ __forceinline__ float tanh_(float x) {
    float y; asm("tanh.approx.f32 %0, %1;" : "=f"(y) : "f"(x)); return y;
}
// pack two f32 -> f16x2 (first arg -> low half)
__device__ __forceinline__ u32 packh2(float lo, float hi) {
    u32 r; asm("cvt.rn.f16x2.f32 %0, %1, %2;" : "=r"(r) : "f"(hi), "f"(lo)); return r;
}

// ---------------- mma / ldmatrix wrappers (plain sm_80+ PTX) ----------------
__device__ __forceinline__ u32 smem_u32(const void* p) {
    u32 a; asm("{ .reg .u64 t; cvta.to.shared.u64 t, %1; cvt.u32.u64 %0, t; }"
               : "=r"(a) : "l"(p));
    return a;
}
__device__ __forceinline__ void ldm_x4(u32* r, u32 addr) {
    asm volatile("ldmatrix.sync.aligned.m8n8.x4.shared.b16 {%0,%1,%2,%3}, [%4];"
        : "=r"(r[0]), "=r"(r[1]), "=r"(r[2]), "=r"(r[3]) : "r"(addr));
}
__device__ __forceinline__ void ldm_x2(u32* r, u32 addr) {
    asm volatile("ldmatrix.sync.aligned.m8n8.x2.shared.b16 {%0,%1}, [%2];"
        : "=r"(r[0]), "=r"(r[1]) : "r"(addr));
}
__device__ __forceinline__ void mma_f16(float* c, const u32* a, const u32* b) {
    asm volatile(
        "mma.sync.aligned.m16n8k16.row.col.f32.f16.f16.f32 "
        "{%0,%1,%2,%3}, {%4,%5,%6,%7}, {%8,%9}, {%0,%1,%2,%3};"
        : "+f"(c[0]), "+f"(c[1]), "+f"(c[2]), "+f"(c[3])
        : "r"(a[0]), "r"(a[1]), "r"(a[2]), "r"(a[3]), "r"(b[0]), "r"(b[1]));
}

// ---------------- scratch (device globals; no allocations allowed) ----------
__device__ float g_fc [NB * HP * WP];      // final_conf  [b,h,w]
__device__ float g_partial[2048];
__device__ unsigned int g_count;
__device__ unsigned char g_maskh[NB][ND * 80];   // fp16 mask, 0.5-prescaled
__device__ float g_gxT[NB * ND * GSTRIDE];       // gx         [b,n,w]
__device__ float g_gyT[NB * ND * GSTRIDE];       // gy * conf  [b,n,h]

// ---------------- SMEM layout for assemble (bytes) --------------------------
#define SM_B   0                       // mask fp16  [200][80B] = 16000
#define SM_P   16000                   // proto fp16 [128][80B] = 10240
#define SM_GX  26240                   // gx f32     [200][20]  = 16000
#define SM_GY  42240                   // gy f32     [200][12]  = 9600
#define SM_TOTAL 51840

// ---------------- Kernel 0: prep — fp16 mask + gaussian tables --------------
// One block per (b, n): 160 threads. Wide grid -> latency well hidden.
__global__ __launch_bounds__(160)
void prep_kernel(const float* __restrict__ mask,
                 const float* __restrict__ loc,
                 const float* __restrict__ conf) {
    int bn = blockIdx.x;               // b*ND + n
    int b  = bn / ND;
    int n  = bn - b * ND;
    int t  = threadIdx.x;

    float4 l = ((const float4*)loc)[bn];

    if (t < 32) {
        float v = 0.5f * mask[(size_t)bn * NK + t];   // 0.5 for tanh sigmoid
        __half h = __float2half_rn(v);
        *(unsigned short*)&g_maskh[b][n * 80 + 2 * t] = *(unsigned short*)&h;
    }
    if (t < GSTRIDE) {
        float gx = 0.0f, gy = 0.0f;
        if (t < WP) {
            float xs = (t + 0.5f) * (1.0f / (float)WP);
            float s  = fmaxf(l.z, 1e-3f);
            float iv = __fdividef(0.5f, s * s);
            float d  = xs - l.x;
            gx = __expf(-d * d * iv);

            float ys = (t + 0.5f) * (1.0f / (float)HP);
            float sh = fmaxf(l.w, 1e-3f);
            float ih = __fdividef(0.5f, sh * sh);
            float dh = ys - l.y;
            gy = __expf(-dh * dh * ih) * conf[bn];
        }
        g_gxT[(size_t)bn * GSTRIDE + t] = gx;
        g_gyT[(size_t)bn * GSTRIDE + t] = gy;
    }
}

// ---------------- Kernel 1: HMMA assemble + tanh sigmoid + moments ----------
// CTA = 128-pixel tile (8h x 16w) of one batch, 256 threads (8 warps).
// Warp wid owns M rows wid*16..+15 == pixel row h0+wid, cols w0..w0+15.
// c = 0.5 * proto . mask via SINGLE fp16 mma.sync (f32 accum, exact products);
// sigma = 0.5 + 0.5*tanh(c).
__global__ __launch_bounds__(256, 3)
void assemble_kernel(const float* __restrict__ proto) {
    extern __shared__ char smem[];
    u32 sbase = smem_u32(smem);
    int tid  = threadIdx.x;
    int wid  = tid >> 5;
    int lane = tid & 31;
    int b   = blockIdx.z;
    int w0  = blockIdx.x * 16;
    int h0  = blockIdx.y * 8;

    // ---- staging ----
    if (tid < 128) {
        // proto row r -> fp16, 80B-stride rows
        int r  = tid;
        int hh = min(h0 + (r >> 4), HP - 1);
        int ww = min(w0 + (r & 15), WP - 1);
        const float4* ps = (const float4*)(proto +
            ((size_t)(b * HP + hh) * WP + ww) * NK);
        #pragma unroll
        for (int c = 0; c < 4; c++) {
            float4 q0 = ps[2 * c + 0];
            float4 q1 = ps[2 * c + 1];
            uint4 o;
            o.x = packh2(q0.x, q0.y);
            o.y = packh2(q0.z, q0.w);
            o.z = packh2(q1.x, q1.y);
            o.w = packh2(q1.z, q1.w);
            *(uint4*)(smem + SM_P + r * 80 + c * 16) = o;
        }
    } else {
        // copy fp16 mask (16000B) as float4
        int t = tid - 128;
        const float4* src = (const float4*)g_maskh[b];
        for (int j = t; j < 1000; j += 128)
            *(float4*)(smem + SM_B + j * 16) = src[j];
    }
    // gaussian tiles from precomputed tables (coalesced float4)
    {
        const float* gxg = g_gxT + (size_t)b * ND * GSTRIDE + w0;
        const float* gyg = g_gyT + (size_t)b * ND * GSTRIDE + h0;
        for (int i = tid; i < ND * 4; i += 256) {       // gx: [n][20] stride
            int n = i >> 2, j = i & 3;
            float4 v = *(const float4*)(gxg + n * GSTRIDE + 4 * j);
            *(float4*)(smem + SM_GX + (n * 20 + 4 * j) * 4) = v;
        }
        for (int i = tid; i < ND * 2; i += 256) {       // gy: [n][12] stride
            int n = i >> 1, j = i & 1;
            float4 v = *(const float4*)(gyg + n * GSTRIDE + 4 * j);
            *(float4*)(smem + SM_GY + (n * 12 + 4 * j) * 4) = v;
        }
    }
    __syncthreads();

    // ---- A fragments (proto fp16, 16x32), loaded once ----
    u32 a_row_off = (u32)((wid * 16 + (lane & 15)) * 80 + ((lane & 16)));
    u32 a0[4], a1[4];
    ldm_x4(a0, sbase + SM_P + a_row_off);        // k0-15
    ldm_x4(a1, sbase + SM_P + a_row_off + 32);   // k16-31

    u32 b_base = sbase + SM_B + (u32)((lane & 7) * 80 + ((lane & 8) << 1));

    const float* gx_s = (const float*)(smem + SM_GX);
    const float* gy_s = (const float*)(smem + SM_GY);
    int g  = lane >> 2;
    int ca = (lane & 3) * 2;
    const u64 HALF2 = pack2(0.5f, 0.5f);

    u64 s1r0 = 0, s2r0 = 0, s1r1 = 0, s2r1 = 0;

    // double-buffered B fragments: [par][k0(2), k1(2)]
    u32 bb[2][4];
    ldm_x2(bb[0] + 0, b_base + 0);
    ldm_x2(bb[0] + 2, b_base + 32);

    #pragma unroll 2
    for (int nt = 0; nt < 25; nt++) {
        const u32* bc = bb[nt & 1];
        u32*       bn = bb[(nt & 1) ^ 1];
        if (nt < 24) {
            u32 brow = (u32)((nt + 1) * 8 * 80);
            ldm_x2(bn + 0, b_base + brow);
            ldm_x2(bn + 2, b_base + brow + 32);
        }

        float c[4] = {0.f, 0.f, 0.f, 0.f};
        mma_f16(c, a0, bc + 0);
        mma_f16(c, a1, bc + 2);

        // epilogue: c0=(r0,na) c1=(r0,nb) c2=(r1,na) c3=(r1,nb); h row = wid
        int na = nt * 8 + ca, nb_ = na + 1;
        float gya = gy_s[na * 12 + wid];
        float gyb = gy_s[nb_ * 12 + wid];
        float ga0 = gx_s[na * 20 + g]      * gya;
        float gb0 = gx_s[nb_ * 20 + g]     * gyb;
        float ga1 = gx_s[na * 20 + 8 + g]  * gya;
        float gb1 = gx_s[nb_ * 20 + 8 + g] * gyb;

        // sigma = 0.5 + 0.5*tanh(c)   (mask prescaled by 0.5)
        u64 t0 = pack2(tanh_(c[0]), tanh_(c[1]));
        u64 t1 = pack2(tanh_(c[2]), tanh_(c[3]));
        u64 sg0 = fma2_(t0, HALF2, HALF2);
        u64 sg1 = fma2_(t1, HALF2, HALF2);
        u64 mc0 = mul2_(sg0, pack2(ga0, gb0));
        u64 mc1 = mul2_(sg1, pack2(ga1, gb1));
        s1r0 = add2_(s1r0, mc0);
        s2r0 = fma2_(mc0, mc0, s2r0);
        s1r1 = add2_(s1r1, mc1);
        s2r1 = fma2_(mc1, mc1, s2r1);
    }

    float x, y;
    unpack2(s1r0, x, y); float s10 = x + y;
    unpack2(s2r0, x, y); float s20 = x + y;
    unpack2(s1r1, x, y); float s11 = x + y;
    unpack2(s2r1, x, y); float s21 = x + y;

    #pragma unroll
    for (int m = 1; m <= 2; m <<= 1) {
        s10 += __shfl_xor_sync(0xFFFFFFFFu, s10, m);
        s20 += __shfl_xor_sync(0xFFFFFFFFu, s20, m);
        s11 += __shfl_xor_sync(0xFFFFFFFFu, s11, m);
        s21 += __shfl_xor_sync(0xFFFFFFFFu, s21, m);
    }

    if ((lane & 3) == 0) {
        int h = h0 + wid;
        if (h < HP) {
            float* dst = g_fc + (size_t)(b * HP + h) * WP;
            int wa = w0 + g;
            if (wa < WP) {
                float fc = 1.0f - __fdividef(s20, s10 + 1e-6f);
                if (isnan(fc)) fc = 0.0f;
                dst[wa] = fc;
            }
            int wb = w0 + 8 + g;
            if (wb < WP) {
                float fc = 1.0f - __fdividef(s21, s11 + 1e-6f);
                if (isnan(fc)) fc = 0.0f;
                dst[wb] = fc;
            }
        }
    }
}

// ---------------- Kernel C: bilinear 138->550, weighted variance, reduce ----
// 4 pixels per thread; original read as float4 (24 wide loads per thread).
__global__ __launch_bounds__(256)
void finalize_kernel(const float* __restrict__ orig, float* __restrict__ out) {
    int q = blockIdx.x * 256 + threadIdx.x;
    float val = 0.0f;
    if (q < NQUAD) {
        int p0 = 4 * q;

        // per-pixel bilinear setup
        float fys[4], fxs[4];
        int y0c[4], y1c[4], x0c[4], x1c[4];
        #pragma unroll
        for (int px = 0; px < 4; px++) {
            int p = p0 + px;
            int i = p / W0, j = p - i * W0;
            const float scale = (float)HP / (float)H0;
            float sy = (i + 0.5f) * scale - 0.5f;
            float sx = (j + 0.5f) * scale - 0.5f;
            float fy0 = floorf(sy), fx0 = floorf(sx);
            fys[px] = sy - fy0; fxs[px] = sx - fx0;
            int y0 = (int)fy0, x0 = (int)fx0;
            y0c[px] = min(max(y0, 0), HP - 1);
            y1c[px] = min(max(y0 + 1, 0), HP - 1);
            x0c[px] = min(max(x0, 0), WP - 1);
            x1c[px] = min(max(x0 + 1, 0), WP - 1);
        }

        float r[4][NB];
        float tot[4] = {0.f, 0.f, 0.f, 0.f};
        #pragma unroll
        for (int b = 0; b < NB; b++) {
            const float* f = g_fc + (size_t)b * HP * WP;
            #pragma unroll
            for (int px = 0; px < 4; px++) {
                float v00 = __ldg(f + y0c[px] * WP + x0c[px]);
                float v01 = __ldg(f + y0c[px] * WP + x1c[px]);
                float v10 = __ldg(f + y1c[px] * WP + x0c[px]);
                float v11 = __ldg(f + y1c[px] * WP + x1c[px]);
                float v0 = v00 + (v01 - v00) * fxs[px];
                float v1 = v10 + (v11 - v10) * fxs[px];
                float rv = v0 + (v1 - v0) * fys[px];
                r[px][b] = rv;
                tot[px] += rv;
            }
        }
        float it[4], ite[4];
        #pragma unroll
        for (int px = 0; px < 4; px++) {
            it[px]  = __fdividef(1.0f, tot[px]);
            ite[px] = __fdividef(1.0f, tot[px] + 1e-6f);
        }

        #pragma unroll
        for (int c = 0; c < NC; c++) {
            float4 ov[NB];
            #pragma unroll
            for (int b = 0; b < NB; b++)
                ov[b] = __ldg((const float4*)(orig +
                         ((size_t)(b * NC + c)) * (H0 * W0) + p0));
            #pragma unroll
            for (int px = 0; px < 4; px++) {
                float o[NB];
                #pragma unroll
                for (int b = 0; b < NB; b++) {
                    float4 v = ov[b];
                    o[b] = (px == 0) ? v.x : (px == 1) ? v.y : (px == 2) ? v.z : v.w;
                }
                float s = 0.0f;
                #pragma unroll
                for (int b = 0; b < NB; b++) s = fmaf(o[b], r[px][b], s);
                float wm = s * it[px];
                float acc = 0.0f;
                #pragma unroll
                for (int b = 0; b < NB; b++) {
                    float d = o[b] - wm;
                    acc = fmaf(d * d, r[px][b], acc);
                }
                val += acc * ite[px];
            }
        }
        val *= (float)NB / (float)NK;
    }

    __shared__ float red[256];
    red[threadIdx.x] = val;
    __syncthreads();
    #pragma unroll
    for (int s = 128; s > 0; s >>= 1) {
        if (threadIdx.x < s) red[threadIdx.x] += red[threadIdx.x + s];
        __syncthreads();
    }

    __shared__ bool is_last;
    if (threadIdx.x == 0) {
        g_partial[blockIdx.x] = red[0];
        __threadfence();
        unsigned int prev = atomicInc(&g_count, NBLK_FIN - 1);
        is_last = (prev == NBLK_FIN - 1);
    }
    __syncthreads();

    if (is_last) {
        __threadfence();
        float s = 0.0f;
        for (int i = threadIdx.x; i < NBLK_FIN; i += 256) s += g_partial[i];
        red[threadIdx.x] = s;
        __syncthreads();
        #pragma unroll
        for (int st = 128; st > 0; st >>= 1) {
            if (threadIdx.x < st) red[threadIdx.x] += red[threadIdx.x + st];
            __syncthreads();
        }
        if (threadIdx.x == 0) out[0] = red[0];
    }
}

// ---------------- launch ------------------------------------------------------
extern "C" void kernel_launch(void* const* d_in, const int* in_sizes, int n_in,
                              void* d_out, int out_size) {
    const float* original = (const float*)d_in[0];  // [8,3,550,550]
    const float* loc      = (const float*)d_in[1];  // [8,200,4]
    const float* maskp    = (const float*)d_in[2];  // [8,200,32]
    const float* confp    = (const float*)d_in[3];  // [8,200]
    const float* proto    = (const float*)d_in[4];  // [8,138,138,32]
    float* out = (float*)d_out;

    static bool attr_set = false;
    if (!attr_set) {
        cudaFuncSetAttribute(assemble_kernel,
                             cudaFuncAttributeMaxDynamicSharedMemorySize,
                             SM_TOTAL);
        attr_set = true;
    }

    prep_kernel<<<NB * ND, 160>>>(maskp, loc, confp);

    dim3 gB((WP + 15) / 16, (HP + 7) / 8, NB);   // 9 x 18 x 8 = 1296
    assemble_kernel<<<gB, 256, SM_TOTAL>>>(proto);

    finalize_kernel<<<NBLK_FIN, 256>>>(original, out);
}